// round 10
// baseline (speedup 1.0000x reference)
#include <cuda_runtime.h>
#include <cstdint>

#define TWX  32
#define TY   16
#define SYY  18                  // TY + 2 halo rows
#define RW   34                  // row stride in pixels
#define PL   616                 // plane stride (words); 616 % 32 == 8 -> banks {0,8,16,24}+g
#define SMB_W (8 * PL)           // 4928 words
#define B_WORDS (9 * 128)        // 1152
#define SMEM_BYTES ((SMB_W + B_WORDS) * 4)   // 24320

static __device__ __forceinline__ uint32_t pack_h2(float lo, float hi) {
    uint32_t r;
    asm("cvt.rn.f16x2.f32 %0, %1, %2;" : "=r"(r) : "f"(hi), "f"(lo));  // 2nd src -> low half
    return r;
}

static __device__ __forceinline__ void mma_f16(float* c,
                                               uint32_t a0, uint32_t a1, uint32_t a2, uint32_t a3,
                                               uint32_t b0, uint32_t b1) {
    asm volatile(
        "mma.sync.aligned.m16n8k16.row.col.f32.f16.f16.f32 "
        "{%0,%1,%2,%3}, {%4,%5,%6,%7}, {%8,%9}, {%0,%1,%2,%3};"
        : "+f"(c[0]), "+f"(c[1]), "+f"(c[2]), "+f"(c[3])
        : "r"(a0), "r"(a1), "r"(a2), "r"(a3), "r"(b0), "r"(b1));
}

__global__ __launch_bounds__(256, 2)
void conv_mma_kernel(const float* __restrict__ x,
                     const float* __restrict__ wg,
                     float* __restrict__ out)
{
    extern __shared__ uint32_t sm[];
    const int tid = threadIdx.x, wid = tid >> 5, lane = tid & 31;
    const int g = lane >> 2, t = lane & 3;
    const int x0 = blockIdx.x * TWX;
    const int y0 = blockIdx.y * TY;
    const int b  = blockIdx.z;

    // ---- weights -> smem B, LDS.128-friendly layout ----
    // lane (g,t) fragment for a tap = 4 consecutive words at word (4g+t)*4:
    //   j0:(co=g,p=t) j1:(co=g,p=t+4) j2:(co=g+8,p=t) j3:(co=g+8,p=t+4)
    if (tid < 128) {
        const int co = tid >> 3, p = tid & 7;
        const float* w0 = wg + (co * 16 + 2 * p) * 9;        // cin = 2p
        const float* w1 = w0 + 9;                            // cin = 2p+1
        const uint32_t sa = SMB_W + ((co & 7) * 4 + (p & 3)) * 4 + (co >> 3) * 2 + (p >> 2);
#pragma unroll
        for (int tap = 0; tap < 9; tap++)
            sm[sa + tap * 128] = pack_h2(w0[tap], w1[tap]);  // low = cin 2p (k even)
    }

    // ---- input tile -> smem A: 8 cin-pair planes of packed half2; warp = plane ----
    {
        const int p = wid;                                   // 8 warps, 8 pair-planes
        const float* r0 = x + ((size_t)(b * 16 + 2 * p) * 1024 + (y0 - 1)) * 1024;
        const float* r1 = r0 + 1024 * 1024;                  // cin 2p+1
        const int gx_m = x0 - 1 + lane;
        const bool xok_m = (unsigned)gx_m < 1024u;
        const int gx_e = x0 + 31 + lane;
        const bool xok_e = (lane < 2) && ((unsigned)gx_e < 1024u);
        uint32_t sa = p * PL;
#pragma unroll
        for (int yy = 0; yy < SYY; yy++) {
            const int gy = y0 - 1 + yy;
            const bool yok = (unsigned)gy < 1024u;
            float v0 = 0.f, v1 = 0.f, e0 = 0.f, e1 = 0.f;
            if (yok && xok_m) { v0 = r0[gx_m]; v1 = r1[gx_m]; }
            if (yok && xok_e) { e0 = r0[gx_e]; e1 = r1[gx_e]; }
            sm[sa + lane] = pack_h2(v0, v1);
            if (lane < 2) sm[sa + 32 + lane] = pack_h2(e0, e1);
            r0 += 1024; r1 += 1024;
            sa += RW;
        }
    }
    __syncthreads();

    // ---- B fragments cached once per warp: 9 x LDS.128 ----
    uint4 Bv[9];
    {
        const uint4* pb4 = (const uint4*)(sm + SMB_W);
#pragma unroll
        for (int tap = 0; tap < 9; tap++)
            Bv[tap] = pb4[tap * 32 + lane];
    }

    // ---- mainloop: warp owns rows yw, yw+1; A fragments cached per input row li ----
    float C[2][2][2][4];                                     // [r][xh][nt][q]
#pragma unroll
    for (int r = 0; r < 2; r++)
#pragma unroll
        for (int xh = 0; xh < 2; xh++)
#pragma unroll
            for (int nt = 0; nt < 2; nt++)
#pragma unroll
                for (int q = 0; q < 4; q++) C[r][xh][nt][q] = 0.0f;

    const int yw = 2 * wid;
    const uint32_t* pa = sm + t * PL + yw * RW + g;

#pragma unroll
    for (int li = 0; li < 4; li++) {                         // input row yw + li
        uint32_t av[2][3][2][2];                             // [xh][dx][kh][mh]
#pragma unroll
        for (int xh = 0; xh < 2; xh++)
#pragma unroll
            for (int dx = 0; dx < 3; dx++) {
                const int o = li * RW + xh * 16 + dx;        // compile-time constant
                av[xh][dx][0][0] = pa[o];                    // m=g,   k lo
                av[xh][dx][0][1] = pa[o + 8];                // m=g+8, k lo
                av[xh][dx][1][0] = pa[o + 4 * PL];           // m=g,   k hi
                av[xh][dx][1][1] = pa[o + 4 * PL + 8];       // m=g+8, k hi
            }
#pragma unroll
        for (int r = 0; r < 2; r++) {
            const int dy = li - r;
            if (dy >= 0 && dy <= 2) {
#pragma unroll
                for (int dx = 0; dx < 3; dx++) {
                    const int tap = dy * 3 + dx;
#pragma unroll
                    for (int xh = 0; xh < 2; xh++) {
                        mma_f16(C[r][xh][0],
                                av[xh][dx][0][0], av[xh][dx][0][1],
                                av[xh][dx][1][0], av[xh][dx][1][1],
                                Bv[tap].x, Bv[tap].y);
                        mma_f16(C[r][xh][1],
                                av[xh][dx][0][0], av[xh][dx][0][1],
                                av[xh][dx][1][0], av[xh][dx][1][1],
                                Bv[tap].z, Bv[tap].w);
                    }
                }
            }
        }
    }

    // ---- epilogue ----
    float* ob = out + (size_t)b * 16 * 1024 * 1024;
#pragma unroll
    for (int r = 0; r < 2; r++) {
        const int y = y0 + yw + r;
#pragma unroll
        for (int xh = 0; xh < 2; xh++) {
            const int xg = x0 + xh * 16 + g;
#pragma unroll
            for (int nt = 0; nt < 2; nt++) {
                const int co = nt * 8 + 2 * t;
                float* p0 = ob + ((size_t)co * 1024 + y) * 1024;
                float* p1 = p0 + 1024 * 1024;                // co + 1
                p0[xg]     = C[r][xh][nt][0];
                p1[xg]     = C[r][xh][nt][1];
                p0[xg + 8] = C[r][xh][nt][2];
                p1[xg + 8] = C[r][xh][nt][3];
            }
        }
    }
}

extern "C" void kernel_launch(void* const* d_in, const int* in_sizes, int n_in,
                              void* d_out, int out_size) {
    const float* x = (const float*)d_in[0];
    const float* w = (const float*)d_in[1];
    if (n_in >= 2 && in_sizes[0] == 16 * 16 * 9) {           // defensive order check
        const float* tp = x; x = w; w = tp;
    }
    float* out = (float*)d_out;

    cudaFuncSetAttribute(conv_mma_kernel,
                         cudaFuncAttributeMaxDynamicSharedMemorySize, SMEM_BYTES);
    dim3 grid(1024 / TWX, 1024 / TY, 8);
    conv_mma_kernel<<<grid, 256, SMEM_BYTES>>>(x, w, out);
}

// round 11
// speedup vs baseline: 1.0684x; 1.0684x over previous
#include <cuda_runtime.h>
#include <cstdint>

#define TWX  32
#define TY   16
#define SYY  18                  // TY + 2 halo rows
#define RW   34                  // row stride in pixels
#define PL   616                 // plane stride (words); 616 % 32 == 8 -> banks {0,8,16,24}+g
#define SMB_W (8 * PL)           // 4928 words
#define B_WORDS (9 * 128)        // 1152
#define SMEM_BYTES ((SMB_W + B_WORDS) * 4)   // 24320

static __device__ __forceinline__ uint32_t pack_h2(float lo, float hi) {
    uint32_t r;
    asm("cvt.rn.f16x2.f32 %0, %1, %2;" : "=r"(r) : "f"(hi), "f"(lo));  // 2nd src -> low half
    return r;
}

static __device__ __forceinline__ void mma_f16(float* c,
                                               uint32_t a0, uint32_t a1, uint32_t a2, uint32_t a3,
                                               uint32_t b0, uint32_t b1) {
    asm volatile(
        "mma.sync.aligned.m16n8k16.row.col.f32.f16.f16.f32 "
        "{%0,%1,%2,%3}, {%4,%5,%6,%7}, {%8,%9}, {%0,%1,%2,%3};"
        : "+f"(c[0]), "+f"(c[1]), "+f"(c[2]), "+f"(c[3])
        : "r"(a0), "r"(a1), "r"(a2), "r"(a3), "r"(b0), "r"(b1));
}

__global__ __launch_bounds__(256, 3)
void conv_mma_kernel(const float* __restrict__ x,
                     const float* __restrict__ wg,
                     float* __restrict__ out)
{
    extern __shared__ uint32_t sm[];
    const int tid = threadIdx.x, wid = tid >> 5, lane = tid & 31;
    const int g = lane >> 2, t = lane & 3;
    const int x0 = blockIdx.x * TWX;
    const int y0 = blockIdx.y * TY;
    const int b  = blockIdx.z;

    // ---- weights -> smem B, LDS.128-friendly layout ----
    // lane (g,t) fragment for a tap = 4 consecutive words at word (4g+t)*4:
    //   j0:(co=g,p=t) j1:(co=g,p=t+4) j2:(co=g+8,p=t) j3:(co=g+8,p=t+4)
    if (tid < 128) {
        const int co = tid >> 3, p = tid & 7;
        const float* w0 = wg + (co * 16 + 2 * p) * 9;        // cin = 2p
        const float* w1 = w0 + 9;                            // cin = 2p+1
        const uint32_t sa = SMB_W + ((co & 7) * 4 + (p & 3)) * 4 + (co >> 3) * 2 + (p >> 2);
#pragma unroll
        for (int tap = 0; tap < 9; tap++)
            sm[sa + tap * 128] = pack_h2(w0[tap], w1[tap]);  // low = cin 2p (k even)
    }

    // ---- input tile -> smem A: 8 cin-pair planes of packed half2; warp = plane ----
    {
        const int p = wid;                                   // 8 warps, 8 pair-planes
        const float* r0 = x + ((size_t)(b * 16 + 2 * p) * 1024 + (y0 - 1)) * 1024;
        const float* r1 = r0 + 1024 * 1024;                  // cin 2p+1
        const int gx_m = x0 - 1 + lane;
        const bool xok_m = (unsigned)gx_m < 1024u;
        const int gx_e = x0 + 31 + lane;
        const bool xok_e = (lane < 2) && ((unsigned)gx_e < 1024u);
        uint32_t sa = p * PL;
#pragma unroll
        for (int yy = 0; yy < SYY; yy++) {
            const int gy = y0 - 1 + yy;
            const bool yok = (unsigned)gy < 1024u;
            float v0 = 0.f, v1 = 0.f, e0 = 0.f, e1 = 0.f;
            if (yok && xok_m) { v0 = r0[gx_m]; v1 = r1[gx_m]; }
            if (yok && xok_e) { e0 = r0[gx_e]; e1 = r1[gx_e]; }
            sm[sa + lane] = pack_h2(v0, v1);
            if (lane < 2) sm[sa + 32 + lane] = pack_h2(e0, e1);
            r0 += 1024; r1 += 1024;
            sa += RW;
        }
    }
    __syncthreads();

    // ---- B fragments cached once per warp: 9 x LDS.128 ----
    uint4 Bv[9];
    {
        const uint4* pb4 = (const uint4*)(sm + SMB_W);
#pragma unroll
        for (int tap = 0; tap < 9; tap++)
            Bv[tap] = pb4[tap * 32 + lane];
    }

    // ---- mainloop: warp owns rows yw, yw+1; A cached per (li, xh) ----
    float C[2][2][2][4];                                     // [r][xh][nt][q]
#pragma unroll
    for (int r = 0; r < 2; r++)
#pragma unroll
        for (int xh = 0; xh < 2; xh++)
#pragma unroll
            for (int nt = 0; nt < 2; nt++)
#pragma unroll
                for (int q = 0; q < 4; q++) C[r][xh][nt][q] = 0.0f;

    const int yw = 2 * wid;
    const uint32_t* pa = sm + t * PL + yw * RW + g;

#pragma unroll
    for (int li = 0; li < 4; li++) {                         // input row yw + li
#pragma unroll
        for (int xh = 0; xh < 2; xh++) {
            uint32_t av[3][2][2];                            // [dx][kh][mh] — 12 regs
#pragma unroll
            for (int dx = 0; dx < 3; dx++) {
                const int o = li * RW + xh * 16 + dx;        // compile-time constant
                av[dx][0][0] = pa[o];                        // m=g,   k lo
                av[dx][0][1] = pa[o + 8];                    // m=g+8, k lo
                av[dx][1][0] = pa[o + 4 * PL];               // m=g,   k hi
                av[dx][1][1] = pa[o + 4 * PL + 8];           // m=g+8, k hi
            }
#pragma unroll
            for (int r = 0; r < 2; r++) {
                const int dy = li - r;
                if (dy >= 0 && dy <= 2) {
#pragma unroll
                    for (int dx = 0; dx < 3; dx++) {
                        const int tap = dy * 3 + dx;
                        mma_f16(C[r][xh][0],
                                av[dx][0][0], av[dx][0][1],
                                av[dx][1][0], av[dx][1][1],
                                Bv[tap].x, Bv[tap].y);
                        mma_f16(C[r][xh][1],
                                av[dx][0][0], av[dx][0][1],
                                av[dx][1][0], av[dx][1][1],
                                Bv[tap].z, Bv[tap].w);
                    }
                }
            }
        }
    }

    // ---- epilogue ----
    float* ob = out + (size_t)b * 16 * 1024 * 1024;
#pragma unroll
    for (int r = 0; r < 2; r++) {
        const int y = y0 + yw + r;
#pragma unroll
        for (int xh = 0; xh < 2; xh++) {
            const int xg = x0 + xh * 16 + g;
#pragma unroll
            for (int nt = 0; nt < 2; nt++) {
                const int co = nt * 8 + 2 * t;
                float* p0 = ob + ((size_t)co * 1024 + y) * 1024;
                float* p1 = p0 + 1024 * 1024;                // co + 1
                p0[xg]     = C[r][xh][nt][0];
                p1[xg]     = C[r][xh][nt][1];
                p0[xg + 8] = C[r][xh][nt][2];
                p1[xg + 8] = C[r][xh][nt][3];
            }
        }
    }
}

extern "C" void kernel_launch(void* const* d_in, const int* in_sizes, int n_in,
                              void* d_out, int out_size) {
    const float* x = (const float*)d_in[0];
    const float* w = (const float*)d_in[1];
    if (n_in >= 2 && in_sizes[0] == 16 * 16 * 9) {           // defensive order check
        const float* tp = x; x = w; w = tp;
    }
    float* out = (float*)d_out;

    cudaFuncSetAttribute(conv_mma_kernel,
                         cudaFuncAttributeMaxDynamicSharedMemorySize, SMEM_BYTES);
    dim3 grid(1024 / TWX, 1024 / TY, 8);
    conv_mma_kernel<<<grid, 256, SMEM_BYTES>>>(x, w, out);
}